// round 4
// baseline (speedup 1.0000x reference)
#include <cuda_runtime.h>
#include <cuda_bf16.h>
#include <math.h>
#include <stdint.h>

// ---------------- problem constants ----------------
#define MAXN   50000
#define DIM    96
#define KNBR   16
#define NBIAS  15
#define SCALE  0.25f
#define TBL_ROWS 64

typedef unsigned long long ull;

// ---------------- device scratch ----------------
__device__ __align__(16) float g_q[MAXN * DIM];
__device__ __align__(16) float g_k[MAXN * DIM];
__device__ __align__(16) float g_v[MAXN * DIM];
__device__ __align__(16) float g_x[MAXN * DIM];
// tq/tk interleaved bf16: [c][row][24 groups][tq0..3, tk0..3]
__device__ __align__(16) __nv_bfloat16 g_tqk[3 * TBL_ROWS * 192];
// tv fp32 c-major: [c][row][96]
__device__ __align__(16) float g_tv[3 * TBL_ROWS * DIM];
// W_qkv paired: [48][288*2]  (w[2dp][c], w[2dp+1][c])
__device__ __align__(16) float g_wq[48 * 576];
// W_proj paired: [48][96*2]
__device__ __align__(16) float g_wp[48 * 192];
__device__ int g_quant[MAXN];
__device__ unsigned int g_minbits[3];

// ---------------- f32x2 helpers ----------------
__device__ __forceinline__ ull fma2(ull a, ull b, ull c) {
    ull d;
    asm("fma.rn.f32x2 %0, %1, %2, %3;" : "=l"(d) : "l"(a), "l"(b), "l"(c));
    return d;
}
__device__ __forceinline__ float f2sum(ull a) {
    unsigned lo, hi;
    asm("mov.b64 {%0, %1}, %2;" : "=r"(lo), "=r"(hi) : "l"(a));
    return __uint_as_float(lo) + __uint_as_float(hi);
}
__device__ __forceinline__ float2 bf2f(unsigned u) {
    __nv_bfloat162 h = *reinterpret_cast<__nv_bfloat162*>(&u);
    return __bfloat1622float2(h);
}

// ---------------- kernel 0: init min ----------------
__global__ void k_init_min() {
    if (threadIdx.x < 3) g_minbits[threadIdx.x] = 0x7F800000u;
}

// ---------------- kernel 1: xyz min ----------------
__global__ void k_min(const float* __restrict__ xyz, int N) {
    float v0 = INFINITY, v1 = INFINITY, v2 = INFINITY;
    for (int i = blockIdx.x * blockDim.x + threadIdx.x; i < N;
         i += gridDim.x * blockDim.x) {
        v0 = fminf(v0, xyz[i * 3 + 0]);
        v1 = fminf(v1, xyz[i * 3 + 1]);
        v2 = fminf(v2, xyz[i * 3 + 2]);
    }
    #pragma unroll
    for (int m = 16; m >= 1; m >>= 1) {
        v0 = fminf(v0, __shfl_xor_sync(0xFFFFFFFFu, v0, m));
        v1 = fminf(v1, __shfl_xor_sync(0xFFFFFFFFu, v1, m));
        v2 = fminf(v2, __shfl_xor_sync(0xFFFFFFFFu, v2, m));
    }
    if ((threadIdx.x & 31) == 0) {
        atomicMin(&g_minbits[0], __float_as_uint(v0));
        atomicMin(&g_minbits[1], __float_as_uint(v1));
        atomicMin(&g_minbits[2], __float_as_uint(v2));
    }
}

// ---------------- kernel 2: quant + table repack + W repack ----------------
__global__ void k_prep(const float* __restrict__ xyz,
                       const float* __restrict__ shift_ptr,
                       const float* __restrict__ tq,
                       const float* __restrict__ tk,
                       const float* __restrict__ tv,
                       const float* __restrict__ Wq,
                       const float* __restrict__ Wp, int N) {
    int i = blockIdx.x * blockDim.x + threadIdx.x;
    if (i < N) {
        float shift = shift_ptr ? *shift_ptr : 0.0f;
        int packed = 0;
        #pragma unroll
        for (int c = 0; c < 3; c++) {
            float mn = __uint_as_float(g_minbits[c]);
            float m = fmodf(xyz[i * 3 + c] - mn + shift, 4.0f);
            if (m < 0.0f) m += 4.0f;
            int q = (int)floorf(m * 4.0f);
            q = max(0, min(15, q));
            packed |= q << (8 * c);
        }
        g_quant[i] = packed;
    }
    if (i < 3 * TBL_ROWS * DIM) {
        int c = i / (TBL_ROWS * DIM);
        int rem = i % (TBL_ROWS * DIM);
        int r = rem / DIM, dim = rem % DIM;
        int src = (r * DIM + dim) * 3 + c;
        int gdst = (c * TBL_ROWS + r) * 192 + (dim / 4) * 8 + (dim % 4);
        g_tqk[gdst]     = __float2bfloat16(tq[src]);
        g_tqk[gdst + 4] = __float2bfloat16(tk[src]);
        g_tv[(c * TBL_ROWS + r) * DIM + dim] = tv[src];
    }
    if (i < 48 * 576) {
        int dp = i / 576, rem = i % 576;
        int c = rem >> 1, par = rem & 1;
        g_wq[i] = Wq[(2 * dp + par) * 288 + c];
    }
    if (i < 48 * 192) {
        int dp = i / 192, rem = i % 192;
        int c = rem >> 1, par = rem & 1;
        g_wp[i] = Wp[(2 * dp + par) * DIM + c];
    }
}

// ---------------- kernel 3: QKV GEMM, f32x2, 32rows x 96cols / block ----
// 192 threads: rg = t/24 (rows rg*4..+3), cg = t%24 (cols cg*4..+3)
// gridDim.y = 3 selects the q/k/v column tile.
__global__ __launch_bounds__(192) void k_qkv(const float* __restrict__ feats,
                                             const float* __restrict__ b, int N) {
    __shared__ __align__(16) float sf[32 * DIM];
    int row0 = blockIdx.x * 32;
    int ct = blockIdx.y;
    int t = threadIdx.x;
    for (int idx = t; idx < 32 * DIM / 4; idx += 192) {
        int r = idx / 24;
        int row = row0 + r;
        float4 v = (row < N)
            ? reinterpret_cast<const float4*>(&feats[row * DIM])[idx % 24]
            : make_float4(0.f, 0.f, 0.f, 0.f);
        reinterpret_cast<float4*>(sf)[idx] = v;
    }
    __syncthreads();

    int cg = t % 24;
    int rg = t / 24;
    int col0 = ct * DIM + cg * 4;

    ull acc[4][4];
    #pragma unroll
    for (int r = 0; r < 4; r++)
        #pragma unroll
        for (int c = 0; c < 4; c++) acc[r][c] = 0ull;

    const float* srow = &sf[rg * 4 * DIM];
    #pragma unroll 4
    for (int dp = 0; dp < 48; dp++) {
        ulonglong2 w01 = *reinterpret_cast<const ulonglong2*>(&g_wq[dp * 576 + col0 * 2]);
        ulonglong2 w23 = *reinterpret_cast<const ulonglong2*>(&g_wq[dp * 576 + col0 * 2 + 4]);
        #pragma unroll
        for (int r = 0; r < 4; r++) {
            ull s2 = *reinterpret_cast<const ull*>(&srow[r * DIM + 2 * dp]);
            acc[r][0] = fma2(s2, w01.x, acc[r][0]);
            acc[r][1] = fma2(s2, w01.y, acc[r][1]);
            acc[r][2] = fma2(s2, w23.x, acc[r][2]);
            acc[r][3] = fma2(s2, w23.y, acc[r][3]);
        }
    }

    float4 bias = *reinterpret_cast<const float4*>(&b[col0]);
    float* dst = (ct == 0) ? g_q : (ct == 1) ? g_k : g_v;
    float sc = (ct == 0) ? SCALE : 1.0f;
    int ocol = cg * 4;
    #pragma unroll
    for (int r = 0; r < 4; r++) {
        int row = row0 + rg * 4 + r;
        if (row < N) {
            float4 o;
            o.x = (f2sum(acc[r][0]) + bias.x) * sc;
            o.y = (f2sum(acc[r][1]) + bias.y) * sc;
            o.z = (f2sum(acc[r][2]) + bias.z) * sc;
            o.w = (f2sum(acc[r][3]) + bias.w) * sc;
            *reinterpret_cast<float4*>(&dst[row * DIM + ocol]) = o;
        }
    }
}

// ---------------- kernel 4: attention, warp/query, float4 lanes ----------
__global__ __launch_bounds__(256) void k_attn(const int* __restrict__ index_1, int N) {
    int warp = threadIdx.x >> 5;
    int lane = threadIdx.x & 31;
    int i = blockIdx.x * 8 + warp;
    if (i >= N) return;

    int dim0 = (lane < 24) ? 4 * lane : 0;

    float4 q4 = *reinterpret_cast<const float4*>(&g_q[i * DIM + dim0]);
    int qi = g_quant[i];

    int idx = 0, qn = 0;
    if (lane < KNBR) {
        idx = index_1[i * KNBR + lane];
        qn = g_quant[idx];
    }

    float l = 0.f;
    float4 o4 = make_float4(0.f, 0.f, 0.f, 0.f);

    #pragma unroll 2
    for (int j = 0; j < KNBR; j++) {
        int nj = __shfl_sync(0xFFFFFFFFu, idx, j);
        int qj = __shfl_sync(0xFFFFFFFFu, qn, j);
        int rr[3];
        rr[0] = ((qi      ) & 255) - ((qj      ) & 255) + NBIAS;
        rr[1] = ((qi >>  8) & 255) - ((qj >>  8) & 255) + NBIAS;
        rr[2] = ((qi >> 16) & 255) - ((qj >> 16) & 255) + NBIAS;

        float4 k4 = *reinterpret_cast<const float4*>(&g_k[nj * DIM + dim0]);
        float4 v4 = *reinterpret_cast<const float4*>(&g_v[nj * DIM + dim0]);

        float a = q4.x * k4.x;
        a = fmaf(q4.y, k4.y, a);
        a = fmaf(q4.z, k4.z, a);
        a = fmaf(q4.w, k4.w, a);

        #pragma unroll
        for (int c = 0; c < 3; c++) {
            const uint4* tp = reinterpret_cast<const uint4*>(
                &g_tqk[(c * TBL_ROWS + rr[c]) * 192]) + lane;
            uint4 u = *tp;
            float2 tq01 = bf2f(u.x);
            float2 tq23 = bf2f(u.y);
            float2 tk01 = bf2f(u.z);
            float2 tk23 = bf2f(u.w);
            a = fmaf(q4.x, tq01.x, a);
            a = fmaf(q4.y, tq01.y, a);
            a = fmaf(q4.z, tq23.x, a);
            a = fmaf(q4.w, tq23.y, a);
            a = fmaf(k4.x, tk01.x, a);
            a = fmaf(k4.y, tk01.y, a);
            a = fmaf(k4.z, tk23.x, a);
            a = fmaf(k4.w, tk23.y, a);

            float4 tv4 = *reinterpret_cast<const float4*>(
                &g_tv[(c * TBL_ROWS + rr[c]) * DIM + dim0]);
            v4.x += tv4.x; v4.y += tv4.y; v4.z += tv4.z; v4.w += tv4.w;
        }

        a += __shfl_xor_sync(0xFFFFFFFFu, a, 1);
        a += __shfl_xor_sync(0xFFFFFFFFu, a, 2);

        float w = __expf(a);
        l += w;
        o4.x = fmaf(w, v4.x, o4.x);
        o4.y = fmaf(w, v4.y, o4.y);
        o4.z = fmaf(w, v4.z, o4.z);
        o4.w = fmaf(w, v4.w, o4.w);
    }

    if (lane < 24) {
        float rl = __frcp_rn(l);
        float4 x;
        x.x = o4.x * rl; x.y = o4.y * rl; x.z = o4.z * rl; x.w = o4.w * rl;
        *reinterpret_cast<float4*>(&g_x[i * DIM + dim0]) = x;
    }
}

// ---------------- kernel 5: proj GEMM, f32x2, 32rows x 96cols / block ----
__global__ __launch_bounds__(192) void k_proj(const float* __restrict__ b,
                                              float* __restrict__ out, int N) {
    __shared__ __align__(16) float sf[32 * DIM];
    int row0 = blockIdx.x * 32;
    int t = threadIdx.x;
    for (int idx = t; idx < 32 * DIM / 4; idx += 192) {
        int r = idx / 24;
        int row = row0 + r;
        float4 v = (row < N)
            ? reinterpret_cast<const float4*>(&g_x[row * DIM])[idx % 24]
            : make_float4(0.f, 0.f, 0.f, 0.f);
        reinterpret_cast<float4*>(sf)[idx] = v;
    }
    __syncthreads();

    int cg = t % 24;
    int rg = t / 24;
    int col0 = cg * 4;

    ull acc[4][4];
    #pragma unroll
    for (int r = 0; r < 4; r++)
        #pragma unroll
        for (int c = 0; c < 4; c++) acc[r][c] = 0ull;

    const float* srow = &sf[rg * 4 * DIM];
    #pragma unroll 4
    for (int dp = 0; dp < 48; dp++) {
        ulonglong2 w01 = *reinterpret_cast<const ulonglong2*>(&g_wp[dp * 192 + col0 * 2]);
        ulonglong2 w23 = *reinterpret_cast<const ulonglong2*>(&g_wp[dp * 192 + col0 * 2 + 4]);
        #pragma unroll
        for (int r = 0; r < 4; r++) {
            ull s2 = *reinterpret_cast<const ull*>(&srow[r * DIM + 2 * dp]);
            acc[r][0] = fma2(s2, w01.x, acc[r][0]);
            acc[r][1] = fma2(s2, w01.y, acc[r][1]);
            acc[r][2] = fma2(s2, w23.x, acc[r][2]);
            acc[r][3] = fma2(s2, w23.y, acc[r][3]);
        }
    }

    float4 bias = *reinterpret_cast<const float4*>(&b[col0]);
    #pragma unroll
    for (int r = 0; r < 4; r++) {
        int row = row0 + rg * 4 + r;
        if (row < N) {
            float4 o;
            o.x = f2sum(acc[r][0]) + bias.x;
            o.y = f2sum(acc[r][1]) + bias.y;
            o.z = f2sum(acc[r][2]) + bias.z;
            o.w = f2sum(acc[r][3]) + bias.w;
            *reinterpret_cast<float4*>(&out[row * DIM + cg * 4]) = o;
        }
    }
}

// ---------------- launch ----------------
extern "C" void kernel_launch(void* const* d_in, const int* in_sizes, int n_in,
                              void* d_out, int out_size) {
    int p = 0;
    const float* feats = (const float*)d_in[p++];
    const float* xyz   = (const float*)d_in[p++];
    p++;                                                // index_0
    int N = in_sizes[p] - 1; p++;                       // index_0_offsets
    if (p < n_in && in_sizes[p] == 1) p++;              // n_max
    const int* index_1 = (const int*)d_in[p++];
    const float* shift = nullptr;
    if (p < n_in && in_sizes[p] == 1) { shift = (const float*)d_in[p]; p++; }
    const float* W_qkv  = (const float*)d_in[p++];
    const float* b_qkv  = (const float*)d_in[p++];
    const float* tq     = (const float*)d_in[p++];
    const float* tk     = (const float*)d_in[p++];
    const float* tv     = (const float*)d_in[p++];
    const float* W_proj = (const float*)d_in[p++];
    const float* b_proj = (const float*)d_in[p++];
    float* out = (float*)d_out;

    if (N > MAXN) N = MAXN;

    int nrb = (N + 31) / 32;
    k_init_min<<<1, 32>>>();
    k_min<<<128, 256>>>(xyz, N);
    k_prep<<<(N + 255) / 256, 256>>>(xyz, shift, tq, tk, tv, W_qkv, W_proj, N);
    k_qkv<<<dim3(nrb, 3), 192>>>(feats, b_qkv, N);
    k_attn<<<(N + 7) / 8, 256>>>(index_1, N);
    k_proj<<<nrb, 192>>>(b_proj, out, N);
}

// round 5
// speedup vs baseline: 1.0304x; 1.0304x over previous
#include <cuda_runtime.h>
#include <cuda_bf16.h>
#include <math.h>
#include <stdint.h>

// ---------------- problem constants ----------------
#define MAXN   50000
#define DIM    96
#define KNBR   16
#define NBIAS  15
#define SCALE  0.25f
#define TBL_ROWS 64

typedef unsigned long long ull;

// ---------------- device scratch ----------------
__device__ __align__(16) float g_q[MAXN * DIM];
__device__ __align__(16) float g_k[MAXN * DIM];
__device__ __align__(16) float g_v[MAXN * DIM];
__device__ __align__(16) float g_x[MAXN * DIM];
// tq/tk interleaved bf16: [c][row][24 groups][tq0..3, tk0..3]
__device__ __align__(16) __nv_bfloat16 g_tqk[3 * TBL_ROWS * 192];
// tv fp32 c-major: [c][row][96]
__device__ __align__(16) float g_tv[3 * TBL_ROWS * DIM];
// W_qkv paired: [48][288*2]  (w[2dp][c], w[2dp+1][c])
__device__ __align__(16) float g_wq[48 * 576];
// W_proj paired: [48][96*2]
__device__ __align__(16) float g_wp[48 * 192];
__device__ int g_quant[MAXN];
__device__ unsigned int g_minbits[3];

// ---------------- f32x2 helpers ----------------
__device__ __forceinline__ ull fma2(ull a, ull b, ull c) {
    ull d;
    asm("fma.rn.f32x2 %0, %1, %2, %3;" : "=l"(d) : "l"(a), "l"(b), "l"(c));
    return d;
}
__device__ __forceinline__ float f2sum(ull a) {
    unsigned lo, hi;
    asm("mov.b64 {%0, %1}, %2;" : "=r"(lo), "=r"(hi) : "l"(a));
    return __uint_as_float(lo) + __uint_as_float(hi);
}
__device__ __forceinline__ float2 bf2f(unsigned u) {
    __nv_bfloat162 h = *reinterpret_cast<__nv_bfloat162*>(&u);
    return __bfloat1622float2(h);
}

// ---------------- kernel 0: init min ----------------
__global__ void k_init_min() {
    if (threadIdx.x < 3) g_minbits[threadIdx.x] = 0x7F800000u;
}

// ---------------- kernel 1: xyz min ----------------
__global__ void k_min(const float* __restrict__ xyz, int N) {
    float v0 = INFINITY, v1 = INFINITY, v2 = INFINITY;
    for (int i = blockIdx.x * blockDim.x + threadIdx.x; i < N;
         i += gridDim.x * blockDim.x) {
        v0 = fminf(v0, xyz[i * 3 + 0]);
        v1 = fminf(v1, xyz[i * 3 + 1]);
        v2 = fminf(v2, xyz[i * 3 + 2]);
    }
    #pragma unroll
    for (int m = 16; m >= 1; m >>= 1) {
        v0 = fminf(v0, __shfl_xor_sync(0xFFFFFFFFu, v0, m));
        v1 = fminf(v1, __shfl_xor_sync(0xFFFFFFFFu, v1, m));
        v2 = fminf(v2, __shfl_xor_sync(0xFFFFFFFFu, v2, m));
    }
    if ((threadIdx.x & 31) == 0) {
        atomicMin(&g_minbits[0], __float_as_uint(v0));
        atomicMin(&g_minbits[1], __float_as_uint(v1));
        atomicMin(&g_minbits[2], __float_as_uint(v2));
    }
}

// ---------------- kernel 2: quant + table repack + W repack ----------------
__global__ void k_prep(const float* __restrict__ xyz,
                       const float* __restrict__ shift_ptr,
                       const float* __restrict__ tq,
                       const float* __restrict__ tk,
                       const float* __restrict__ tv,
                       const float* __restrict__ Wq,
                       const float* __restrict__ Wp, int N) {
    int i = blockIdx.x * blockDim.x + threadIdx.x;
    if (i < N) {
        float shift = shift_ptr ? *shift_ptr : 0.0f;
        int packed = 0;
        #pragma unroll
        for (int c = 0; c < 3; c++) {
            float mn = __uint_as_float(g_minbits[c]);
            float m = fmodf(xyz[i * 3 + c] - mn + shift, 4.0f);
            if (m < 0.0f) m += 4.0f;
            int q = (int)floorf(m * 4.0f);
            q = max(0, min(15, q));
            packed |= q << (8 * c);
        }
        g_quant[i] = packed;
    }
    if (i < 3 * TBL_ROWS * DIM) {
        int c = i / (TBL_ROWS * DIM);
        int rem = i % (TBL_ROWS * DIM);
        int r = rem / DIM, dim = rem % DIM;
        int src = (r * DIM + dim) * 3 + c;
        int gdst = (c * TBL_ROWS + r) * 192 + (dim / 4) * 8 + (dim % 4);
        g_tqk[gdst]     = __float2bfloat16(tq[src]);
        g_tqk[gdst + 4] = __float2bfloat16(tk[src]);
        g_tv[(c * TBL_ROWS + r) * DIM + dim] = tv[src];
    }
    if (i < 48 * 576) {
        int dp = i / 576, rem = i % 576;
        int c = rem >> 1, par = rem & 1;
        g_wq[i] = Wq[(2 * dp + par) * 288 + c];
    }
    if (i < 48 * 192) {
        int dp = i / 192, rem = i % 192;
        int c = rem >> 1, par = rem & 1;
        g_wp[i] = Wp[(2 * dp + par) * DIM + c];
    }
}

// ---------------- kernel 3: QKV GEMM [N,96]x[96,288], f32x2, 8x4 tile ----
// 288 threads: cg = t%72 (cols cg*4..+3), rg = t/72 (rows rg*8..+7)
// launch_bounds(288,2) caps regs ~112 -> 2 blocks/SM (18 warps).
__global__ __launch_bounds__(288, 2) void k_qkv(const float* __restrict__ feats,
                                                const float* __restrict__ b, int N) {
    __shared__ __align__(16) float sf[32 * DIM];
    int row0 = blockIdx.x * 32;
    int t = threadIdx.x;
    for (int idx = t; idx < 32 * DIM / 4; idx += 288) {
        int r = idx / 24;
        int row = row0 + r;
        float4 v = (row < N)
            ? reinterpret_cast<const float4*>(&feats[row * DIM])[idx % 24]
            : make_float4(0.f, 0.f, 0.f, 0.f);
        reinterpret_cast<float4*>(sf)[idx] = v;
    }
    __syncthreads();

    int cg = t % 72;
    int rg = t / 72;
    int col0 = cg * 4;

    ull acc[8][4];
    #pragma unroll
    for (int r = 0; r < 8; r++)
        #pragma unroll
        for (int c = 0; c < 4; c++) acc[r][c] = 0ull;

    const float* srow = &sf[rg * 8 * DIM];
    #pragma unroll 2
    for (int dp = 0; dp < 48; dp++) {
        ulonglong2 w01 = *reinterpret_cast<const ulonglong2*>(&g_wq[dp * 576 + col0 * 2]);
        ulonglong2 w23 = *reinterpret_cast<const ulonglong2*>(&g_wq[dp * 576 + col0 * 2 + 4]);
        #pragma unroll
        for (int r = 0; r < 8; r++) {
            ull s2 = *reinterpret_cast<const ull*>(&srow[r * DIM + 2 * dp]);
            acc[r][0] = fma2(s2, w01.x, acc[r][0]);
            acc[r][1] = fma2(s2, w01.y, acc[r][1]);
            acc[r][2] = fma2(s2, w23.x, acc[r][2]);
            acc[r][3] = fma2(s2, w23.y, acc[r][3]);
        }
    }

    float4 bias = *reinterpret_cast<const float4*>(&b[col0]);
    int sel = col0 / DIM;
    int ocol = col0 % DIM;
    float* dst = (sel == 0) ? g_q : (sel == 1) ? g_k : g_v;
    float sc = (sel == 0) ? SCALE : 1.0f;
    #pragma unroll
    for (int r = 0; r < 8; r++) {
        int row = row0 + rg * 8 + r;
        if (row < N) {
            float4 o;
            o.x = (f2sum(acc[r][0]) + bias.x) * sc;
            o.y = (f2sum(acc[r][1]) + bias.y) * sc;
            o.z = (f2sum(acc[r][2]) + bias.z) * sc;
            o.w = (f2sum(acc[r][3]) + bias.w) * sc;
            *reinterpret_cast<float4*>(&dst[row * DIM + ocol]) = o;
        }
    }
}

// ---------------- kernel 4: attention, warp/query, float4 lanes ----------
__global__ __launch_bounds__(256) void k_attn(const int* __restrict__ index_1, int N) {
    int warp = threadIdx.x >> 5;
    int lane = threadIdx.x & 31;
    int i = blockIdx.x * 8 + warp;
    if (i >= N) return;

    int dim0 = (lane < 24) ? 4 * lane : 0;

    float4 q4 = *reinterpret_cast<const float4*>(&g_q[i * DIM + dim0]);
    int qi = g_quant[i];

    int idx = 0, qn = 0;
    if (lane < KNBR) {
        idx = index_1[i * KNBR + lane];
        qn = g_quant[idx];
    }

    float l = 0.f;
    float4 o4 = make_float4(0.f, 0.f, 0.f, 0.f);

    #pragma unroll 2
    for (int j = 0; j < KNBR; j++) {
        int nj = __shfl_sync(0xFFFFFFFFu, idx, j);
        int qj = __shfl_sync(0xFFFFFFFFu, qn, j);
        int rr[3];
        rr[0] = ((qi      ) & 255) - ((qj      ) & 255) + NBIAS;
        rr[1] = ((qi >>  8) & 255) - ((qj >>  8) & 255) + NBIAS;
        rr[2] = ((qi >> 16) & 255) - ((qj >> 16) & 255) + NBIAS;

        float4 k4 = *reinterpret_cast<const float4*>(&g_k[nj * DIM + dim0]);
        float4 v4 = *reinterpret_cast<const float4*>(&g_v[nj * DIM + dim0]);

        float a = q4.x * k4.x;
        a = fmaf(q4.y, k4.y, a);
        a = fmaf(q4.z, k4.z, a);
        a = fmaf(q4.w, k4.w, a);

        #pragma unroll
        for (int c = 0; c < 3; c++) {
            const uint4* tp = reinterpret_cast<const uint4*>(
                &g_tqk[(c * TBL_ROWS + rr[c]) * 192]) + lane;
            uint4 u = *tp;
            float2 tq01 = bf2f(u.x);
            float2 tq23 = bf2f(u.y);
            float2 tk01 = bf2f(u.z);
            float2 tk23 = bf2f(u.w);
            a = fmaf(q4.x, tq01.x, a);
            a = fmaf(q4.y, tq01.y, a);
            a = fmaf(q4.z, tq23.x, a);
            a = fmaf(q4.w, tq23.y, a);
            a = fmaf(k4.x, tk01.x, a);
            a = fmaf(k4.y, tk01.y, a);
            a = fmaf(k4.z, tk23.x, a);
            a = fmaf(k4.w, tk23.y, a);

            float4 tv4 = *reinterpret_cast<const float4*>(
                &g_tv[(c * TBL_ROWS + rr[c]) * DIM + dim0]);
            v4.x += tv4.x; v4.y += tv4.y; v4.z += tv4.z; v4.w += tv4.w;
        }

        a += __shfl_xor_sync(0xFFFFFFFFu, a, 1);
        a += __shfl_xor_sync(0xFFFFFFFFu, a, 2);

        float w = __expf(a);
        l += w;
        o4.x = fmaf(w, v4.x, o4.x);
        o4.y = fmaf(w, v4.y, o4.y);
        o4.z = fmaf(w, v4.z, o4.z);
        o4.w = fmaf(w, v4.w, o4.w);
    }

    if (lane < 24) {
        float rl = __frcp_rn(l);
        float4 x;
        x.x = o4.x * rl; x.y = o4.y * rl; x.z = o4.z * rl; x.w = o4.w * rl;
        *reinterpret_cast<float4*>(&g_x[i * DIM + dim0]) = x;
    }
}

// ---------------- kernel 5: proj GEMM [N,96]x[96,96], f32x2, 8x4 tile ----
// 192 threads: cg = t%24 (cols cg*4..+3), rg = t/24 (rows rg*8..+7), 64 rows/block
__global__ __launch_bounds__(192, 3) void k_proj(const float* __restrict__ b,
                                                 float* __restrict__ out, int N) {
    __shared__ __align__(16) float sf[64 * DIM];
    int row0 = blockIdx.x * 64;
    int t = threadIdx.x;
    for (int idx = t; idx < 64 * DIM / 4; idx += 192) {
        int r = idx / 24;
        int row = row0 + r;
        float4 v = (row < N)
            ? reinterpret_cast<const float4*>(&g_x[row * DIM])[idx % 24]
            : make_float4(0.f, 0.f, 0.f, 0.f);
        reinterpret_cast<float4*>(sf)[idx] = v;
    }
    __syncthreads();

    int cg = t % 24;
    int rg = t / 24;
    int col0 = cg * 4;

    ull acc[8][4];
    #pragma unroll
    for (int r = 0; r < 8; r++)
        #pragma unroll
        for (int c = 0; c < 4; c++) acc[r][c] = 0ull;

    const float* srow = &sf[rg * 8 * DIM];
    #pragma unroll 2
    for (int dp = 0; dp < 48; dp++) {
        ulonglong2 w01 = *reinterpret_cast<const ulonglong2*>(&g_wp[dp * 192 + col0 * 2]);
        ulonglong2 w23 = *reinterpret_cast<const ulonglong2*>(&g_wp[dp * 192 + col0 * 2 + 4]);
        #pragma unroll
        for (int r = 0; r < 8; r++) {
            ull s2 = *reinterpret_cast<const ull*>(&srow[r * DIM + 2 * dp]);
            acc[r][0] = fma2(s2, w01.x, acc[r][0]);
            acc[r][1] = fma2(s2, w01.y, acc[r][1]);
            acc[r][2] = fma2(s2, w23.x, acc[r][2]);
            acc[r][3] = fma2(s2, w23.y, acc[r][3]);
        }
    }

    float4 bias = *reinterpret_cast<const float4*>(&b[col0]);
    #pragma unroll
    for (int r = 0; r < 8; r++) {
        int row = row0 + rg * 8 + r;
        if (row < N) {
            float4 o;
            o.x = f2sum(acc[r][0]) + bias.x;
            o.y = f2sum(acc[r][1]) + bias.y;
            o.z = f2sum(acc[r][2]) + bias.z;
            o.w = f2sum(acc[r][3]) + bias.w;
            *reinterpret_cast<float4*>(&out[row * DIM + col0]) = o;
        }
    }
}

// ---------------- launch ----------------
extern "C" void kernel_launch(void* const* d_in, const int* in_sizes, int n_in,
                              void* d_out, int out_size) {
    int p = 0;
    const float* feats = (const float*)d_in[p++];
    const float* xyz   = (const float*)d_in[p++];
    p++;                                                // index_0
    int N = in_sizes[p] - 1; p++;                       // index_0_offsets
    if (p < n_in && in_sizes[p] == 1) p++;              // n_max
    const int* index_1 = (const int*)d_in[p++];
    const float* shift = nullptr;
    if (p < n_in && in_sizes[p] == 1) { shift = (const float*)d_in[p]; p++; }
    const float* W_qkv  = (const float*)d_in[p++];
    const float* b_qkv  = (const float*)d_in[p++];
    const float* tq     = (const float*)d_in[p++];
    const float* tk     = (const float*)d_in[p++];
    const float* tv     = (const float*)d_in[p++];
    const float* W_proj = (const float*)d_in[p++];
    const float* b_proj = (const float*)d_in[p++];
    float* out = (float*)d_out;

    if (N > MAXN) N = MAXN;

    k_init_min<<<1, 32>>>();
    k_min<<<128, 256>>>(xyz, N);
    k_prep<<<(N + 255) / 256, 256>>>(xyz, shift, tq, tk, tv, W_qkv, W_proj, N);
    k_qkv<<<(N + 31) / 32, 288>>>(feats, b_qkv, N);
    k_attn<<<(N + 7) / 8, 256>>>(index_1, N);
    k_proj<<<(N + 63) / 64, 192>>>(b_proj, out, N);
}